// round 6
// baseline (speedup 1.0000x reference)
#include <cuda_runtime.h>
#include <float.h>
#include <math.h>
#include <cstdint>

#define T_   2048
#define D_   1024
#define H_   704
#define E_   16
#define HS_  1408
#define KSEL 4
#define ROUTE_SCALE_ 2.5446f

// ---------------- static device scratch (no runtime allocation) ----------------
__device__ float g_hg[(size_t)E_ * T_ * H_];   // routed gate-proj fp32
__device__ float g_ht[(size_t)E_ * T_ * H_];   // routed swiglu result fp32
__device__ float g_po[(size_t)E_ * T_ * D_];   // routed down-proj fp32
__device__ float g_sg[(size_t)T_ * HS_];       // shared gate-proj fp32
__device__ float g_ss[(size_t)T_ * HS_];       // shared swiglu result fp32
__device__ int   g_cnt[E_];
__device__ int   g_etok[E_ * T_];
__device__ int   g_slot[T_ * KSEL];
__device__ float g_wt[T_ * KSEL];

// int8 2-level quantized tensors + per-row scales
__device__ char  g_xq1[(size_t)T_ * D_],  g_xq2[(size_t)T_ * D_];
__device__ float g_xs[T_];
__device__ char  g_w1q1[(size_t)E_ * H_ * D_], g_w1q2[(size_t)E_ * H_ * D_];
__device__ float g_w1s[E_ * H_];
__device__ char  g_w3q1[(size_t)E_ * H_ * D_], g_w3q2[(size_t)E_ * H_ * D_];
__device__ float g_w3s[E_ * H_];
__device__ char  g_w2q1[(size_t)E_ * D_ * H_], g_w2q2[(size_t)E_ * D_ * H_];
__device__ float g_w2s[E_ * D_];
__device__ char  g_ws1q1[(size_t)HS_ * D_], g_ws1q2[(size_t)HS_ * D_];
__device__ float g_ws1s[HS_];
__device__ char  g_ws3q1[(size_t)HS_ * D_], g_ws3q2[(size_t)HS_ * D_];
__device__ float g_ws3s[HS_];
__device__ char  g_ws2q1[(size_t)D_ * HS_], g_ws2q2[(size_t)D_ * HS_];
__device__ float g_ws2s[D_];
__device__ char  g_htq1[(size_t)E_ * T_ * H_], g_htq2[(size_t)E_ * T_ * H_];
__device__ float g_hts[E_ * T_];
__device__ char  g_ssq1[(size_t)T_ * HS_], g_ssq2[(size_t)T_ * HS_];
__device__ float g_sss[T_];

// ---------------- helpers ----------------
__device__ __forceinline__ uint32_t smem_u32(const void* p) {
    uint32_t a;
    asm("{ .reg .u64 t; cvta.to.shared.u64 t, %1; cvt.u32.u64 %0, t; }" : "=r"(a) : "l"(p));
    return a;
}
#define CPA(dst, src) \
    asm volatile("cp.async.cg.shared.global [%0], [%1], 16;" :: "r"(dst), "l"(src))
#define CPC() asm volatile("cp.async.commit_group;" ::: "memory")
#define CPW(n) asm volatile("cp.async.wait_group %0;" :: "n"(n) : "memory")
#define LDSM4(R, addr) \
    asm volatile("ldmatrix.sync.aligned.m8n8.x4.shared.b16 {%0,%1,%2,%3}, [%4];" \
        : "=r"((R)[0]), "=r"((R)[1]), "=r"((R)[2]), "=r"((R)[3]) : "r"(addr))

__device__ __forceinline__ void imma(int* c, const uint32_t* a, const uint32_t* b) {
    asm volatile(
        "mma.sync.aligned.m16n8k32.row.col.s32.s8.s8.s32 "
        "{%0,%1,%2,%3}, {%4,%5,%6,%7}, {%8,%9}, {%0,%1,%2,%3};"
        : "+r"(c[0]), "+r"(c[1]), "+r"(c[2]), "+r"(c[3])
        : "r"(a[0]), "r"(a[1]), "r"(a[2]), "r"(a[3]), "r"(b[0]), "r"(b[1]));
}

// ---------------- zero counts ----------------
__global__ void zero_cnt_kernel() {
    if (threadIdx.x < E_) g_cnt[threadIdx.x] = 0;
}

// ---------------- fp32 row -> 2-level int8 quantization (warp per row) ----------
__global__ void quant_kernel(const float* __restrict__ in,
                             char* __restrict__ q1, char* __restrict__ q2,
                             float* __restrict__ s, int K,
                             const int* __restrict__ cnt, int rowsPerZ) {
    const int r = blockIdx.x * 8 + (threadIdx.x >> 5);
    const int lane = threadIdx.x & 31;
    if (cnt) {
        int e = r / rowsPerZ, tr = r - e * rowsPerZ;
        int lim = (cnt[e] + 127) & ~127;
        if (tr >= lim) return;
    }
    const float4* row = (const float4*)(in + (size_t)r * K);
    const int K4 = K >> 2;
    float4 buf[11];
    int n = 0;
    float m = 0.f;
    for (int i = lane; i < K4; i += 32) {
        float4 v = row[i];
        buf[n++] = v;
        m = fmaxf(m, fmaxf(fmaxf(fabsf(v.x), fabsf(v.y)), fmaxf(fabsf(v.z), fabsf(v.w))));
    }
#pragma unroll
    for (int o = 16; o; o >>= 1) m = fmaxf(m, __shfl_xor_sync(0xffffffffu, m, o));
    const float sc = fmaxf(m, 1e-30f) * (1.f / 127.f);
    const float inv = 1.f / sc;
    if (lane == 0) s[r] = sc;
    char4* q1p = (char4*)(q1 + (size_t)r * K);
    char4* q2p = (char4*)(q2 + (size_t)r * K);
    n = 0;
    for (int i = lane; i < K4; i += 32) {
        float4 v = buf[n++];
        float t0 = v.x * inv, t1 = v.y * inv, t2 = v.z * inv, t3 = v.w * inv;
        int a0 = __float2int_rn(t0), a1 = __float2int_rn(t1);
        int a2 = __float2int_rn(t2), a3 = __float2int_rn(t3);
        int b0 = __float2int_rn((t0 - (float)a0) * 128.f);
        int b1 = __float2int_rn((t1 - (float)a1) * 128.f);
        int b2 = __float2int_rn((t2 - (float)a2) * 128.f);
        int b3 = __float2int_rn((t3 - (float)a3) * 128.f);
        q1p[i] = make_char4((char)a0, (char)a1, (char)a2, (char)a3);
        q2p[i] = make_char4((char)b0, (char)b1, (char)b2, (char)b3);
    }
}

// ---------------- gate: logits + DeepSeek-V3 routing + dispatch ----------------
__global__ void gate_kernel(const float* __restrict__ x,
                            const float* __restrict__ gw,
                            const float* __restrict__ gb) {
    __shared__ __align__(16) float xs[8][D_];
    const int warp = threadIdx.x >> 5;
    const int lane = threadIdx.x & 31;
    const int t = blockIdx.x * 8 + warp;

    const float* xr = x + (size_t)t * D_;
    for (int i = lane; i < D_ / 4; i += 32)
        ((float4*)xs[warp])[i] = ((const float4*)xr)[i];
    __syncwarp();

    float lgv[E_];
#pragma unroll
    for (int e = 0; e < E_; e++) {
        const float* wr = gw + (size_t)e * D_;
        float p = 0.f;
        for (int i = lane; i < D_; i += 32) p += xs[warp][i] * wr[i];
#pragma unroll
        for (int o = 16; o; o >>= 1) p += __shfl_xor_sync(0xffffffffu, p, o);
        lgv[e] = p;
    }

    if (lane == 0) {
        float sc[E_], r[E_];
#pragma unroll
        for (int e = 0; e < E_; e++) {
            sc[e] = 1.f / (1.f + expf(-lgv[e]));
            r[e]  = sc[e] + gb[e];
        }
        float gs[4];
#pragma unroll
        for (int g = 0; g < 4; g++) {
            float m1 = -FLT_MAX, m2 = -FLT_MAX;
#pragma unroll
            for (int j = 0; j < 4; j++) {
                float v = r[4 * g + j];
                if (v > m1) { m2 = m1; m1 = v; }
                else if (v > m2) { m2 = v; }
            }
            gs[g] = m1 + m2;
        }
        int g1 = 0;
#pragma unroll
        for (int g = 1; g < 4; g++) if (gs[g] > gs[g1]) g1 = g;
        int g2 = -1;
#pragma unroll
        for (int g = 0; g < 4; g++) {
            if (g == g1) continue;
            if (g2 < 0 || gs[g] > gs[g2]) g2 = g;
        }
#pragma unroll
        for (int e = 0; e < E_; e++) {
            int g = e >> 2;
            if (g != g1 && g != g2) r[e] = -FLT_MAX;
        }
        int idx[KSEL];
        float wsum = 0.f;
#pragma unroll
        for (int k = 0; k < KSEL; k++) {
            int b = 0; float bv = -FLT_MAX;
#pragma unroll
            for (int e = 0; e < E_; e++)
                if (r[e] > bv) { bv = r[e]; b = e; }
            idx[k] = b;
            r[b] = -FLT_MAX;
            wsum += sc[b];
        }
        wsum = fmaxf(wsum, 1e-9f);
#pragma unroll
        for (int k = 0; k < KSEL; k++) {
            int e = idx[k];
            float wk = sc[e] / wsum * ROUTE_SCALE_;
            int pos = atomicAdd(&g_cnt[e], 1);
            g_etok[e * T_ + pos] = t;
            g_slot[t * KSEL + k] = e * T_ + pos;
            g_wt[t * KSEL + k]   = wk;
        }
    }
}

// ---------------- int8 2-level GEMM: C[M,N] = A[M,K] * B[N,K]^T -----------------
// CTA tile 128x64, k-chunk 64 bytes. 256 threads = 8 warps (4m x 2n), warp 32x32.
// 3-stage cp.async pipeline. MODE 0: C = deq. MODE 1: C = silu(GC)*deq.
#define PITCH 80
#define ASTG  (128 * PITCH)           // 10240
#define BSTG  (64 * PITCH)            // 5120
#define STG   (2 * ASTG + 2 * BSTG)   // 30720
#define SCOFF (3 * STG)               // 92160
#define QSMEM (SCOFF + 192 * 4)       // 92928

template <int MODE>
__global__ __launch_bounds__(256) void int8_gemm(
    const char* __restrict__ Aq1, const char* __restrict__ Aq2,
    const float* __restrict__ As, long long aZ, int aSZ,
    const char* __restrict__ Bq1, const char* __restrict__ Bq2,
    const float* __restrict__ Bs, long long bZ, int bSZ,
    float* __restrict__ C, const float* __restrict__ GC, long long cZ,
    int N, int Kd, int M, const int* __restrict__ cnt, const int* __restrict__ gather) {
    extern __shared__ char smem[];
    const uint32_t sb = smem_u32(smem);
    const int tid = threadIdx.x;
    const int z = blockIdx.z;
    const int Me = cnt ? cnt[z] : M;
    const int m0 = blockIdx.y * 128;
    if (m0 >= Me) return;
    const int n0 = blockIdx.x * 64;

    // ---- scale staging ----
    if (tid < 128) {
        int r = m0 + tid;
        int gr = r;
        if (gather) gr = gather[z * T_ + (r < Me ? r : Me - 1)];
        ((float*)(smem + SCOFF))[tid] = As[(size_t)z * aSZ + gr];
    } else if (tid < 192) {
        ((float*)(smem + SCOFF))[tid] = Bs[(size_t)z * bSZ + n0 + tid - 128];
    }

    // ---- load-side mapping: thread -> rows (lr, lr+64) x seg for A; row lr for B ----
    const int lr = tid >> 2, seg = tid & 3;
    int ar0 = m0 + lr, ar1 = m0 + lr + 64;
    if (gather) {
        ar0 = gather[z * T_ + (ar0 < Me ? ar0 : Me - 1)];
        ar1 = gather[z * T_ + (ar1 < Me ? ar1 : Me - 1)];
    }
    const char* a0q1 = Aq1 + (size_t)z * aZ + (size_t)ar0 * Kd;
    const char* a1q1 = Aq1 + (size_t)z * aZ + (size_t)ar1 * Kd;
    const char* a0q2 = Aq2 + (size_t)z * aZ + (size_t)ar0 * Kd;
    const char* a1q2 = Aq2 + (size_t)z * aZ + (size_t)ar1 * Kd;
    const char* bp1 = Bq1 + (size_t)z * bZ + (size_t)(n0 + lr) * Kd;
    const char* bp2 = Bq2 + (size_t)z * bZ + (size_t)(n0 + lr) * Kd;

    const uint32_t dA = sb + (uint32_t)lr * PITCH + (uint32_t)seg * 16;

#define LOAD_STAGE(s, kt) do { \
        const int _ko = (kt) * 64 + seg * 16; \
        const uint32_t _o = (uint32_t)(s) * STG; \
        CPA(dA + _o,                        a0q1 + _ko); \
        CPA(dA + _o + 64 * PITCH,           a1q1 + _ko); \
        CPA(dA + _o + ASTG,                 a0q2 + _ko); \
        CPA(dA + _o + ASTG + 64 * PITCH,    a1q2 + _ko); \
        CPA(dA + _o + 2 * ASTG,             bp1 + _ko); \
        CPA(dA + _o + 2 * ASTG + BSTG,      bp2 + _ko); \
    } while (0)

    // ---- compute-side mapping ----
    const int lane = tid & 31, wid = tid >> 5;
    const int wm = (wid & 3) * 32;
    const int wn = (wid >> 2) * 32;
    uint32_t aoffs[2], boffs[2];
#pragma unroll
    for (int mf = 0; mf < 2; mf++)
        aoffs[mf] = (uint32_t)(wm + mf * 16 + (lane & 15)) * PITCH + (uint32_t)(lane >> 4) * 16;
#pragma unroll
    for (int p = 0; p < 2; p++)
        boffs[p] = (uint32_t)(wn + p * 16 + ((lane >> 4) & 1) * 8 + (lane & 7)) * PITCH
                 + (uint32_t)((lane >> 3) & 1) * 16;

    int acc1[2][4][4], acc2[2][4][4];
#pragma unroll
    for (int i = 0; i < 2; i++)
#pragma unroll
        for (int j = 0; j < 4; j++)
#pragma unroll
            for (int q = 0; q < 4; q++) { acc1[i][j][q] = 0; acc2[i][j][q] = 0; }

    const int KT = Kd >> 6;
    LOAD_STAGE(0, 0); CPC();
    LOAD_STAGE(1, 1); CPC();

    int sbuf = 0;
    for (int kt = 0; kt < KT; kt++) {
        if (kt + 1 < KT) { CPW(1); } else { CPW(0); }
        __syncthreads();
        if (kt + 2 < KT) {
            int ns = sbuf + 2; if (ns >= 3) ns -= 3;
            LOAD_STAGE(ns, kt + 2); CPC();
        }
        const uint32_t base = sb + (uint32_t)sbuf * STG;
#pragma unroll
        for (int sl = 0; sl < 2; sl++) {
            const uint32_t so = (uint32_t)sl * 32;
            uint32_t a1f[2][4], a2f[2][4], b1f[2][4], b2f[2][4];
#pragma unroll
            for (int mf = 0; mf < 2; mf++) {
                LDSM4(a1f[mf], base + aoffs[mf] + so);
                LDSM4(a2f[mf], base + ASTG + aoffs[mf] + so);
            }
#pragma unroll
            for (int p = 0; p < 2; p++) {
                LDSM4(b1f[p], base + 2 * ASTG + boffs[p] + so);
                LDSM4(b2f[p], base + 2 * ASTG + BSTG + boffs[p] + so);
            }
#pragma unroll
            for (int mf = 0; mf < 2; mf++) {
#pragma unroll
                for (int nf = 0; nf < 4; nf++) {
                    const uint32_t* bb1 = &b1f[nf >> 1][(nf & 1) * 2];
                    const uint32_t* bb2 = &b2f[nf >> 1][(nf & 1) * 2];
                    imma(acc1[mf][nf], a1f[mf], bb1);
                    imma(acc2[mf][nf], a1f[mf], bb2);
                    imma(acc2[mf][nf], a2f[mf], bb1);
                }
            }
        }
        sbuf++; if (sbuf >= 3) sbuf = 0;
    }
#undef LOAD_STAGE

    // ---- epilogue: dequant (+ optional silu(GC) gate) ----
    const float* sAp = (const float*)(smem + SCOFF);
    const float* sBp = sAp + 128;
    const int r0 = lane >> 2, c0 = (lane & 3) * 2;
#pragma unroll
    for (int mf = 0; mf < 2; mf++) {
#pragma unroll
        for (int nf = 0; nf < 4; nf++) {
            const int rr = wm + mf * 16 + r0;
            const int cc = wn + nf * 8 + c0;
            const float sa0 = sAp[rr], sa1 = sAp[rr + 8];
            const float sb0 = sBp[cc], sb1 = sBp[cc + 1];
            float v00 = sa0 * sb0 * ((float)acc1[mf][nf][0] + (float)acc2[mf][nf][0] * 0.0078125f);
            float v01 = sa0 * sb1 * ((float)acc1[mf][nf][1] + (float)acc2[mf][nf][1] * 0.0078125f);
            float v10 = sa1 * sb0 * ((float)acc1[mf][nf][2] + (float)acc2[mf][nf][2] * 0.0078125f);
            float v11 = sa1 * sb1 * ((float)acc1[mf][nf][3] + (float)acc2[mf][nf][3] * 0.0078125f);
            const size_t off0 = (size_t)(m0 + rr) * N + n0 + cc;
            const size_t off1 = (size_t)(m0 + rr + 8) * N + n0 + cc;
            if (MODE == 1) {
                const float* Gz = GC + (size_t)z * cZ;
                float2 gA = *(const float2*)(Gz + off0);
                float2 gB = *(const float2*)(Gz + off1);
                v00 *= gA.x / (1.f + expf(-gA.x));
                v01 *= gA.y / (1.f + expf(-gA.y));
                v10 *= gB.x / (1.f + expf(-gB.x));
                v11 *= gB.y / (1.f + expf(-gB.y));
            }
            float* Cz = C + (size_t)z * cZ;
            *(float2*)(Cz + off0) = make_float2(v00, v01);
            *(float2*)(Cz + off1) = make_float2(v10, v11);
        }
    }
}

// ---------------- combine: out += sum_k w_k * pair_out[slot_k] ----------------
__global__ void combine_kernel(float* __restrict__ out) {
    int t = blockIdx.x;
    int c = threadIdx.x;
    float4 a = ((float4*)out)[(size_t)t * (D_ / 4) + c];
#pragma unroll
    for (int k = 0; k < KSEL; k++) {
        int s = g_slot[t * KSEL + k];
        float wk = g_wt[t * KSEL + k];
        float4 v = ((const float4*)g_po)[(size_t)s * (D_ / 4) + c];
        a.x += wk * v.x; a.y += wk * v.y; a.z += wk * v.z; a.w += wk * v.w;
    }
    ((float4*)out)[(size_t)t * (D_ / 4) + c] = a;
}

// ---------------- launch ----------------
#define SYMA(p, s) cudaGetSymbolAddress((void**)&p, s)

extern "C" void kernel_launch(void* const* d_in, const int* in_sizes, int n_in,
                              void* d_out, int out_size) {
    (void)in_sizes; (void)n_in; (void)out_size;
    const float* x   = (const float*)d_in[0];
    const float* gw  = (const float*)d_in[1];
    const float* gb  = (const float*)d_in[2];
    const float* w1  = (const float*)d_in[3];
    const float* w3  = (const float*)d_in[4];
    const float* w2  = (const float*)d_in[5];
    const float* ws1 = (const float*)d_in[6];
    const float* ws3 = (const float*)d_in[7];
    const float* ws2 = (const float*)d_in[8];
    float* out = (float*)d_out;

    cudaFuncSetAttribute(int8_gemm<0>, cudaFuncAttributeMaxDynamicSharedMemorySize, QSMEM);
    cudaFuncSetAttribute(int8_gemm<1>, cudaFuncAttributeMaxDynamicSharedMemorySize, QSMEM);

    float *hg, *ht, *po, *sg, *ss;
    int *cnt, *etok;
    char *xq1, *xq2, *w1q1, *w1q2, *w3q1, *w3q2, *w2q1, *w2q2;
    char *ws1q1, *ws1q2, *ws3q1, *ws3q2, *ws2q1, *ws2q2, *htq1, *htq2, *ssq1, *ssq2;
    float *xs, *w1s, *w3s, *w2s, *ws1s, *ws3s, *ws2s, *hts, *sss;
    SYMA(hg, g_hg); SYMA(ht, g_ht); SYMA(po, g_po); SYMA(sg, g_sg); SYMA(ss, g_ss);
    SYMA(cnt, g_cnt); SYMA(etok, g_etok);
    SYMA(xq1, g_xq1); SYMA(xq2, g_xq2); SYMA(xs, g_xs);
    SYMA(w1q1, g_w1q1); SYMA(w1q2, g_w1q2); SYMA(w1s, g_w1s);
    SYMA(w3q1, g_w3q1); SYMA(w3q2, g_w3q2); SYMA(w3s, g_w3s);
    SYMA(w2q1, g_w2q1); SYMA(w2q2, g_w2q2); SYMA(w2s, g_w2s);
    SYMA(ws1q1, g_ws1q1); SYMA(ws1q2, g_ws1q2); SYMA(ws1s, g_ws1s);
    SYMA(ws3q1, g_ws3q1); SYMA(ws3q2, g_ws3q2); SYMA(ws3s, g_ws3s);
    SYMA(ws2q1, g_ws2q1); SYMA(ws2q2, g_ws2q2); SYMA(ws2s, g_ws2s);
    SYMA(htq1, g_htq1); SYMA(htq2, g_htq2); SYMA(hts, g_hts);
    SYMA(ssq1, g_ssq1); SYMA(ssq2, g_ssq2); SYMA(sss, g_sss);

    // quantize inputs & weights (independent of gate)
    quant_kernel<<<T_ / 8, 256>>>(x, xq1, xq2, xs, D_, nullptr, 0);
    quant_kernel<<<E_ * H_ / 8, 256>>>(w1, w1q1, w1q2, w1s, D_, nullptr, 0);
    quant_kernel<<<E_ * H_ / 8, 256>>>(w3, w3q1, w3q2, w3s, D_, nullptr, 0);
    quant_kernel<<<E_ * D_ / 8, 256>>>(w2, w2q1, w2q2, w2s, H_, nullptr, 0);
    quant_kernel<<<HS_ / 8, 256>>>(ws1, ws1q1, ws1q2, ws1s, D_, nullptr, 0);
    quant_kernel<<<HS_ / 8, 256>>>(ws3, ws3q1, ws3q2, ws3s, D_, nullptr, 0);
    quant_kernel<<<D_ / 8, 256>>>(ws2, ws2q1, ws2q2, ws2s, HS_, nullptr, 0);

    zero_cnt_kernel<<<1, 32>>>();
    gate_kernel<<<T_ / 8, 256>>>(x, gw, gb);

    const long long xZ = 0LL, wZ = (long long)H_ * D_, w2Z = (long long)D_ * H_;
    const long long hZ = (long long)T_ * H_, poZ = (long long)T_ * D_;

    // routed gate proj -> hg fp32
    int8_gemm<0><<<dim3(H_ / 64, T_ / 128, E_), 256, QSMEM>>>(
        xq1, xq2, xs, xZ, 0, w1q1, w1q2, w1s, wZ, H_,
        hg, nullptr, hZ, H_, D_, 0, cnt, etok);
    // routed up proj fused with swiglu -> ht fp32
    int8_gemm<1><<<dim3(H_ / 64, T_ / 128, E_), 256, QSMEM>>>(
        xq1, xq2, xs, xZ, 0, w3q1, w3q2, w3s, wZ, H_,
        ht, hg, hZ, H_, D_, 0, cnt, etok);
    // quantize ht (active tiles only)
    quant_kernel<<<E_ * T_ / 8, 256>>>(ht, htq1, htq2, hts, H_, cnt, T_);
    // routed down proj -> po fp32
    int8_gemm<0><<<dim3(D_ / 64, T_ / 128, E_), 256, QSMEM>>>(
        htq1, htq2, hts, hZ, T_, w2q1, w2q2, w2s, w2Z, D_,
        po, nullptr, poZ, D_, H_, 0, cnt, nullptr);

    // shared FFN
    int8_gemm<0><<<dim3(HS_ / 64, T_ / 128, 1), 256, QSMEM>>>(
        xq1, xq2, xs, 0LL, 0, ws1q1, ws1q2, ws1s, 0LL, 0,
        sg, nullptr, 0LL, HS_, D_, T_, nullptr, nullptr);
    int8_gemm<1><<<dim3(HS_ / 64, T_ / 128, 1), 256, QSMEM>>>(
        xq1, xq2, xs, 0LL, 0, ws3q1, ws3q2, ws3s, 0LL, 0,
        ss, sg, 0LL, HS_, D_, T_, nullptr, nullptr);
    quant_kernel<<<T_ / 8, 256>>>(ss, ssq1, ssq2, sss, HS_, nullptr, 0);
    int8_gemm<0><<<dim3(D_ / 64, T_ / 128, 1), 256, QSMEM>>>(
        ssq1, ssq2, sss, 0LL, 0, ws2q1, ws2q2, ws2s, 0LL, 0,
        out, nullptr, 0LL, D_, HS_, T_, nullptr, nullptr);

    combine_kernel<<<T_, 256>>>(out);
}

// round 7
// speedup vs baseline: 3.6216x; 3.6216x over previous
#include <cuda_runtime.h>
#include <cuda_bf16.h>
#include <float.h>
#include <math.h>
#include <cstdint>

#define T_   2048
#define D_   1024
#define H_   704
#define E_   16
#define HS_  1408
#define KSEL 4
#define ROUTE_SCALE_ 2.5446f

// ---------------- static device scratch ----------------
__device__ float g_po[(size_t)E_ * T_ * D_];
__device__ int   g_cnt[E_];
__device__ int   g_etok[E_ * T_];
__device__ int   g_slot[T_ * KSEL];
__device__ float g_wt[T_ * KSEL];

__device__ __nv_bfloat16 g_xh[(size_t)T_ * D_],  g_xl[(size_t)T_ * D_];
__device__ __nv_bfloat16 g_w1h[(size_t)E_ * H_ * D_], g_w1l[(size_t)E_ * H_ * D_];
__device__ __nv_bfloat16 g_w3h[(size_t)E_ * H_ * D_], g_w3l[(size_t)E_ * H_ * D_];
__device__ __nv_bfloat16 g_w2h[(size_t)E_ * D_ * H_], g_w2l[(size_t)E_ * D_ * H_];
__device__ __nv_bfloat16 g_ws1h[(size_t)HS_ * D_], g_ws1l[(size_t)HS_ * D_];
__device__ __nv_bfloat16 g_ws3h[(size_t)HS_ * D_], g_ws3l[(size_t)HS_ * D_];
__device__ __nv_bfloat16 g_ws2h[(size_t)D_ * HS_], g_ws2l[(size_t)D_ * HS_];
__device__ __nv_bfloat16 g_hth[(size_t)E_ * T_ * H_], g_htl[(size_t)E_ * T_ * H_];
__device__ __nv_bfloat16 g_ssh[(size_t)T_ * HS_], g_ssl[(size_t)T_ * HS_];

// ---------------- helpers ----------------
__device__ __forceinline__ uint32_t smem_u32(const void* p) {
    uint32_t a;
    asm("{ .reg .u64 t; cvta.to.shared.u64 t, %1; cvt.u32.u64 %0, t; }" : "=r"(a) : "l"(p));
    return a;
}
#define CPA(dst, src) \
    asm volatile("cp.async.cg.shared.global [%0], [%1], 16;" :: "r"(dst), "l"(src))
#define CPC() asm volatile("cp.async.commit_group;" ::: "memory")
#define CPW(n) asm volatile("cp.async.wait_group %0;" :: "n"(n) : "memory")
#define LDSM4(R, addr) \
    asm volatile("ldmatrix.sync.aligned.m8n8.x4.shared.b16 {%0,%1,%2,%3}, [%4];" \
        : "=r"((R)[0]), "=r"((R)[1]), "=r"((R)[2]), "=r"((R)[3]) : "r"(addr))

__device__ __forceinline__ void mma16816(float* c, const uint32_t* a, const uint32_t* b) {
    asm volatile(
        "mma.sync.aligned.m16n8k16.row.col.f32.bf16.bf16.f32 "
        "{%0,%1,%2,%3}, {%4,%5,%6,%7}, {%8,%9}, {%0,%1,%2,%3};"
        : "+f"(c[0]), "+f"(c[1]), "+f"(c[2]), "+f"(c[3])
        : "r"(a[0]), "r"(a[1]), "r"(a[2]), "r"(a[3]), "r"(b[0]), "r"(b[1]));
}
__device__ __forceinline__ float silu_(float v) { return v / (1.f + expf(-v)); }

// ---------------- zero counts ----------------
__global__ void zero_cnt_kernel() {
    if (threadIdx.x < E_) g_cnt[threadIdx.x] = 0;
}

// ---------------- fp32 -> bf16 hi/lo split ----------------
__global__ void conv_kernel(const float* __restrict__ in,
                            __nv_bfloat16* __restrict__ hi,
                            __nv_bfloat16* __restrict__ lo, size_t n8) {
    size_t i = (size_t)blockIdx.x * blockDim.x + threadIdx.x;
    if (i >= n8) return;
    float4 v0 = ((const float4*)in)[2 * i];
    float4 v1 = ((const float4*)in)[2 * i + 1];
    float f[8] = {v0.x, v0.y, v0.z, v0.w, v1.x, v1.y, v1.z, v1.w};
    __nv_bfloat16 h[8], l[8];
#pragma unroll
    for (int j = 0; j < 8; j++) {
        h[j] = __float2bfloat16(f[j]);
        l[j] = __float2bfloat16(f[j] - __bfloat162float(h[j]));
    }
    ((uint4*)hi)[i] = *(uint4*)h;
    ((uint4*)lo)[i] = *(uint4*)l;
}

// ---------------- gate ----------------
__global__ void gate_kernel(const float* __restrict__ x,
                            const float* __restrict__ gw,
                            const float* __restrict__ gb) {
    __shared__ __align__(16) float xs[8][D_];
    const int warp = threadIdx.x >> 5;
    const int lane = threadIdx.x & 31;
    const int t = blockIdx.x * 8 + warp;

    const float* xr = x + (size_t)t * D_;
    for (int i = lane; i < D_ / 4; i += 32)
        ((float4*)xs[warp])[i] = ((const float4*)xr)[i];
    __syncwarp();

    float lgv[E_];
#pragma unroll
    for (int e = 0; e < E_; e++) {
        const float* wr = gw + (size_t)e * D_;
        float p = 0.f;
        for (int i = lane; i < D_; i += 32) p += xs[warp][i] * wr[i];
#pragma unroll
        for (int o = 16; o; o >>= 1) p += __shfl_xor_sync(0xffffffffu, p, o);
        lgv[e] = p;
    }

    if (lane == 0) {
        float sc[E_], r[E_];
#pragma unroll
        for (int e = 0; e < E_; e++) {
            sc[e] = 1.f / (1.f + expf(-lgv[e]));
            r[e]  = sc[e] + gb[e];
        }
        float gs[4];
#pragma unroll
        for (int g = 0; g < 4; g++) {
            float m1 = -FLT_MAX, m2 = -FLT_MAX;
#pragma unroll
            for (int j = 0; j < 4; j++) {
                float v = r[4 * g + j];
                if (v > m1) { m2 = m1; m1 = v; }
                else if (v > m2) { m2 = v; }
            }
            gs[g] = m1 + m2;
        }
        int g1 = 0;
#pragma unroll
        for (int g = 1; g < 4; g++) if (gs[g] > gs[g1]) g1 = g;
        int g2 = -1;
#pragma unroll
        for (int g = 0; g < 4; g++) {
            if (g == g1) continue;
            if (g2 < 0 || gs[g] > gs[g2]) g2 = g;
        }
#pragma unroll
        for (int e = 0; e < E_; e++) {
            int g = e >> 2;
            if (g != g1 && g != g2) r[e] = -FLT_MAX;
        }
        int idx[KSEL];
        float wsum = 0.f;
#pragma unroll
        for (int k = 0; k < KSEL; k++) {
            int b = 0; float bv = -FLT_MAX;
#pragma unroll
            for (int e = 0; e < E_; e++)
                if (r[e] > bv) { bv = r[e]; b = e; }
            idx[k] = b;
            r[b] = -FLT_MAX;
            wsum += sc[b];
        }
        wsum = fmaxf(wsum, 1e-9f);
#pragma unroll
        for (int k = 0; k < KSEL; k++) {
            int e = idx[k];
            float wk = sc[e] / wsum * ROUTE_SCALE_;
            int pos = atomicAdd(&g_cnt[e], 1);
            g_etok[e * T_ + pos] = t;
            g_slot[t * KSEL + k] = e * T_ + pos;
            g_wt[t * KSEL + k]   = wk;
        }
    }
}

// ================= phase 1: dual GEMM (gate & up) + SwiGLU, bf16x3 =============
// Tile M=64, N=64, K=1024 fixed. z<16: routed expert (gathered x @ w1/w3^T).
// z==16: shared (x @ ws1/ws3^T). Output: swiglu result as bf16 hi/lo.
// 8 warps = 2m x 4n, warp tile 32x16. 2-stage cp.async.
#define PITCH 80
#define AMAT  5120                  // 64 * 80
#define GA_STAGE (6 * AMAT)         // Ah, Al, B1h, B1l, B3h, B3l
#define GA_SMEM  (2 * GA_STAGE)     // 61440

__global__ __launch_bounds__(256) void gemm_gu() {
    const int z = blockIdx.z;
    const bool sh = (z == E_);
    const int nt = sh ? (HS_ / 64) : (H_ / 64);
    if (blockIdx.x >= nt) return;
    const int Me = sh ? T_ : g_cnt[z];
    const int m0 = blockIdx.y * 64;
    if (m0 >= Me) return;
    const int n0 = blockIdx.x * 64;
    const int N = sh ? HS_ : H_;

    extern __shared__ char smem[];
    const uint32_t sb = smem_u32(smem);
    const int tid = threadIdx.x;

    // ---- load mapping: thread -> row (tid>>2), seg (tid&3) for all 6 matrices
    const int r = tid >> 2, seg = tid & 3;
    int ar = m0 + r;
    if (!sh) ar = g_etok[z * T_ + (ar < Me ? ar : Me - 1)];
    const __nv_bfloat16* aph = g_xh + (size_t)ar * D_;
    const __nv_bfloat16* apl = g_xl + (size_t)ar * D_;
    const size_t brow = sh ? (size_t)(n0 + r) : ((size_t)z * H_ + n0 + r);
    const __nv_bfloat16* b1h = (sh ? g_ws1h : g_w1h) + brow * D_;
    const __nv_bfloat16* b1l = (sh ? g_ws1l : g_w1l) + brow * D_;
    const __nv_bfloat16* b3h = (sh ? g_ws3h : g_w3h) + brow * D_;
    const __nv_bfloat16* b3l = (sh ? g_ws3l : g_w3l) + brow * D_;

    const uint32_t dst = sb + (uint32_t)r * PITCH + (uint32_t)seg * 16;

#define LOAD_GU(s, kt) do { \
        const int _ko = (kt) * 32 + seg * 8; \
        const uint32_t _o = (uint32_t)(s) * GA_STAGE; \
        CPA(dst + _o,            aph + _ko); \
        CPA(dst + _o + AMAT,     apl + _ko); \
        CPA(dst + _o + 2 * AMAT, b1h + _ko); \
        CPA(dst + _o + 3 * AMAT, b1l + _ko); \
        CPA(dst + _o + 4 * AMAT, b3h + _ko); \
        CPA(dst + _o + 5 * AMAT, b3l + _ko); \
    } while (0)

    // ---- compute mapping ----
    const int lane = tid & 31, wid = tid >> 5;
    const int wm = (wid & 1) * 32;
    const int wn = (wid >> 1) * 16;
    const uint32_t a_rowoff = (uint32_t)(wm + (lane & 15)) * PITCH + (uint32_t)(lane >> 4) * 16;
    const uint32_t b_rowoff = (uint32_t)(wn + ((lane >> 4) & 1) * 8 + (lane & 7)) * PITCH
                            + (uint32_t)((lane >> 3) & 1) * 16;

    float acc1[2][2][4], acc3[2][2][4];
#pragma unroll
    for (int i = 0; i < 2; i++)
#pragma unroll
        for (int j = 0; j < 2; j++)
#pragma unroll
            for (int q = 0; q < 4; q++) { acc1[i][j][q] = 0.f; acc3[i][j][q] = 0.f; }

    const int KT = D_ / 32;   // 32 chunks
    LOAD_GU(0, 0); CPC();

    for (int kt = 0; kt < KT; kt++) {
        if (kt + 1 < KT) { LOAD_GU((kt + 1) & 1, kt + 1); CPC(); CPW(1); }
        else             { CPW(0); }
        __syncthreads();
        const uint32_t base = sb + (uint32_t)(kt & 1) * GA_STAGE;
#pragma unroll
        for (int kk = 0; kk < 2; kk++) {
            const uint32_t kb = (uint32_t)kk * 32;
            uint32_t ah[2][4], al[2][4];
#pragma unroll
            for (int mf = 0; mf < 2; mf++) {
                const uint32_t ao = base + a_rowoff + (uint32_t)mf * (16 * PITCH) + kb;
                LDSM4(ah[mf], ao);
                LDSM4(al[mf], ao + AMAT);
            }
            uint32_t bh[4], bl[4];
            // gate (w1)
            LDSM4(bh, base + 2 * AMAT + b_rowoff + kb);
            LDSM4(bl, base + 3 * AMAT + b_rowoff + kb);
#pragma unroll
            for (int mf = 0; mf < 2; mf++) {
#pragma unroll
                for (int nf = 0; nf < 2; nf++) {
                    mma16816(acc1[mf][nf], ah[mf], &bh[nf * 2]);
                    mma16816(acc1[mf][nf], ah[mf], &bl[nf * 2]);
                    mma16816(acc1[mf][nf], al[mf], &bh[nf * 2]);
                }
            }
            // up (w3)
            LDSM4(bh, base + 4 * AMAT + b_rowoff + kb);
            LDSM4(bl, base + 5 * AMAT + b_rowoff + kb);
#pragma unroll
            for (int mf = 0; mf < 2; mf++) {
#pragma unroll
                for (int nf = 0; nf < 2; nf++) {
                    mma16816(acc3[mf][nf], ah[mf], &bh[nf * 2]);
                    mma16816(acc3[mf][nf], ah[mf], &bl[nf * 2]);
                    mma16816(acc3[mf][nf], al[mf], &bh[nf * 2]);
                }
            }
        }
        __syncthreads();
    }
#undef LOAD_GU

    // ---- epilogue: swiglu -> bf16 hi/lo ----
    __nv_bfloat16* OH = sh ? g_ssh : g_hth;
    __nv_bfloat16* OL = sh ? g_ssl : g_htl;
    const size_t rowBase = sh ? 0 : (size_t)z * T_;
#pragma unroll
    for (int mf = 0; mf < 2; mf++) {
#pragma unroll
        for (int nf = 0; nf < 2; nf++) {
            const int rr = wm + mf * 16 + (lane >> 2);
            const int cc = n0 + wn + nf * 8 + (lane & 3) * 2;
            float s0 = silu_(acc1[mf][nf][0]) * acc3[mf][nf][0];
            float s1 = silu_(acc1[mf][nf][1]) * acc3[mf][nf][1];
            float s2 = silu_(acc1[mf][nf][2]) * acc3[mf][nf][2];
            float s3 = silu_(acc1[mf][nf][3]) * acc3[mf][nf][3];
            __nv_bfloat16 h0 = __float2bfloat16(s0), h1 = __float2bfloat16(s1);
            __nv_bfloat16 h2 = __float2bfloat16(s2), h3 = __float2bfloat16(s3);
            const size_t o0 = (rowBase + m0 + rr) * (size_t)N + cc;
            const size_t o1 = (rowBase + m0 + rr + 8) * (size_t)N + cc;
            *(__nv_bfloat162*)(OH + o0) = __nv_bfloat162(h0, h1);
            *(__nv_bfloat162*)(OH + o1) = __nv_bfloat162(h2, h3);
            *(__nv_bfloat162*)(OL + o0) = __nv_bfloat162(
                __float2bfloat16(s0 - __bfloat162float(h0)),
                __float2bfloat16(s1 - __bfloat162float(h1)));
            *(__nv_bfloat162*)(OL + o1) = __nv_bfloat162(
                __float2bfloat16(s2 - __bfloat162float(h2)),
                __float2bfloat16(s3 - __bfloat162float(h3)));
        }
    }
}

// ================= phase 2: down proj, bf16x3 =============
// Tile M=64, N=128. z<16: ht[z] @ w2[z]^T (K=704) -> po. z==16: ss @ ws2^T (K=1408) -> out.
#define BMAT 10240                   // 128 * 80
#define GB_STAGE (2 * AMAT + 2 * BMAT)   // 30720
#define GB_SMEM  (2 * GB_STAGE)          // 61440

__global__ __launch_bounds__(256) void gemm_dn(float* __restrict__ outp) {
    const int z = blockIdx.z;
    const bool sh = (z == E_);
    const int Me = sh ? T_ : g_cnt[z];
    const int m0 = blockIdx.y * 64;
    if (m0 >= Me) return;
    const int n0 = blockIdx.x * 128;
    const int Kd = sh ? HS_ : H_;

    extern __shared__ char smem[];
    const uint32_t sb = smem_u32(smem);
    const int tid = threadIdx.x;

    // A: row tid>>2 (64 rows), seg tid&3 -> 2 cpa. B: row tid>>1 (128), 2 segs -> 4 cpa.
    const int r = tid >> 2, seg = tid & 3;
    const size_t arow = sh ? (size_t)(m0 + r) : ((size_t)z * T_ + m0 + r);
    const __nv_bfloat16* aph = (sh ? g_ssh : g_hth) + arow * Kd;
    const __nv_bfloat16* apl = (sh ? g_ssl : g_htl) + arow * Kd;
    const int rb = tid >> 1, bs2 = (tid & 1) * 2;
    const size_t browk = sh ? (size_t)(n0 + rb) : ((size_t)z * D_ + n0 + rb);
    const __nv_bfloat16* bph = (sh ? g_ws2h : g_w2h) + browk * Kd;
    const __nv_bfloat16* bpl = (sh ? g_ws2l : g_w2l) + browk * Kd;

    const uint32_t dA = sb + (uint32_t)r * PITCH + (uint32_t)seg * 16;
    const uint32_t dB = sb + 2 * AMAT + (uint32_t)rb * PITCH;

#define LOAD_DN(s, kt) do { \
        const int _ka = (kt) * 32 + seg * 8; \
        const int _kb0 = (kt) * 32 + (bs2) * 8; \
        const int _kb1 = (kt) * 32 + (bs2 + 1) * 8; \
        const uint32_t _o = (uint32_t)(s) * GB_STAGE; \
        CPA(dA + _o,            aph + _ka); \
        CPA(dA + _o + AMAT,     apl + _ka); \
        CPA(dB + _o + (uint32_t)(bs2) * 16,            bph + _kb0); \
        CPA(dB + _o + (uint32_t)(bs2 + 1) * 16,        bph + _kb1); \
        CPA(dB + _o + BMAT + (uint32_t)(bs2) * 16,     bpl + _kb0); \
        CPA(dB + _o + BMAT + (uint32_t)(bs2 + 1) * 16, bpl + _kb1); \
    } while (0)

    const int lane = tid & 31, wid = tid >> 5;
    const int wm = (wid & 1) * 32;
    const int wn = (wid >> 1) * 32;
    const uint32_t a_rowoff = (uint32_t)(wm + (lane & 15)) * PITCH + (uint32_t)(lane >> 4) * 16;
    const uint32_t b_rowoff = (uint32_t)(wn + ((lane >> 4) & 1) * 8 + (lane & 7)) * PITCH
                            + (uint32_t)((lane >> 3) & 1) * 16;

    float acc[2][4][4];
#pragma unroll
    for (int i = 0; i < 2; i++)
#pragma unroll
        for (int j = 0; j < 4; j++)
#pragma unroll
            for (int q = 0; q < 4; q++) acc[i][j][q] = 0.f;

    const int KT = Kd / 32;
    LOAD_DN(0, 0); CPC();

    for (int kt = 0; kt < KT; kt++) {
        if (kt + 1 < KT) { LOAD_DN((kt + 1) & 1, kt + 1); CPC(); CPW(1); }
        else             { CPW(0); }
        __syncthreads();
        const uint32_t base = sb + (uint32_t)(kt & 1) * GB_STAGE;
#pragma unroll
        for (int kk = 0; kk < 2; kk++) {
            const uint32_t kb = (uint32_t)kk * 32;
            uint32_t ah[2][4], al[2][4];
#pragma unroll
            for (int mf = 0; mf < 2; mf++) {
                const uint32_t ao = base + a_rowoff + (uint32_t)mf * (16 * PITCH) + kb;
                LDSM4(ah[mf], ao);
                LDSM4(al[mf], ao + AMAT);
            }
            uint32_t bh_[2][4], bl_[2][4];
#pragma unroll
            for (int p = 0; p < 2; p++) {
                const uint32_t bo = base + 2 * AMAT + b_rowoff + (uint32_t)p * (16 * PITCH) + kb;
                LDSM4(bh_[p], bo);
                LDSM4(bl_[p], bo + BMAT);
            }
#pragma unroll
            for (int mf = 0; mf < 2; mf++) {
#pragma unroll
                for (int nf = 0; nf < 4; nf++) {
                    const uint32_t* bh2 = &bh_[nf >> 1][(nf & 1) * 2];
                    const uint32_t* bl2 = &bl_[nf >> 1][(nf & 1) * 2];
                    mma16816(acc[mf][nf], ah[mf], bh2);
                    mma16816(acc[mf][nf], ah[mf], bl2);
                    mma16816(acc[mf][nf], al[mf], bh2);
                }
            }
        }
        __syncthreads();
    }
#undef LOAD_DN

    float* C = sh ? outp : (g_po + (size_t)z * T_ * D_);
#pragma unroll
    for (int mf = 0; mf < 2; mf++) {
#pragma unroll
        for (int nf = 0; nf < 4; nf++) {
            const int rr = m0 + wm + mf * 16 + (lane >> 2);
            const int cc = n0 + wn + nf * 8 + (lane & 3) * 2;
            *(float2*)(C + (size_t)rr * D_ + cc)       = make_float2(acc[mf][nf][0], acc[mf][nf][1]);
            *(float2*)(C + (size_t)(rr + 8) * D_ + cc) = make_float2(acc[mf][nf][2], acc[mf][nf][3]);
        }
    }
}

// ---------------- combine ----------------
__global__ void combine_kernel(float* __restrict__ out) {
    int t = blockIdx.x;
    int c = threadIdx.x;
    float4 a = ((float4*)out)[(size_t)t * (D_ / 4) + c];
#pragma unroll
    for (int k = 0; k < KSEL; k++) {
        int s = g_slot[t * KSEL + k];
        float wk = g_wt[t * KSEL + k];
        float4 v = ((const float4*)g_po)[(size_t)s * (D_ / 4) + c];
        a.x += wk * v.x; a.y += wk * v.y; a.z += wk * v.z; a.w += wk * v.w;
    }
    ((float4*)out)[(size_t)t * (D_ / 4) + c] = a;
}

// ---------------- launch ----------------
static void conv_launch(const float* in, __nv_bfloat16* hi, __nv_bfloat16* lo, size_t n) {
    size_t n8 = n / 8;
    conv_kernel<<<(unsigned)((n8 + 255) / 256), 256>>>(in, hi, lo, n8);
}
#define SYMA(p, s) cudaGetSymbolAddress((void**)&p, s)

extern "C" void kernel_launch(void* const* d_in, const int* in_sizes, int n_in,
                              void* d_out, int out_size) {
    (void)in_sizes; (void)n_in; (void)out_size;
    const float* x   = (const float*)d_in[0];
    const float* gw  = (const float*)d_in[1];
    const float* gb  = (const float*)d_in[2];
    const float* w1  = (const float*)d_in[3];
    const float* w3  = (const float*)d_in[4];
    const float* w2  = (const float*)d_in[5];
    const float* ws1 = (const float*)d_in[6];
    const float* ws3 = (const float*)d_in[7];
    const float* ws2 = (const float*)d_in[8];
    float* out = (float*)d_out;

    cudaFuncSetAttribute(gemm_gu, cudaFuncAttributeMaxDynamicSharedMemorySize, GA_SMEM);
    cudaFuncSetAttribute(gemm_dn, cudaFuncAttributeMaxDynamicSharedMemorySize, GB_SMEM);

    __nv_bfloat16 *xh, *xl, *w1h, *w1l, *w3h, *w3l, *w2h, *w2l;
    __nv_bfloat16 *ws1h, *ws1l, *ws3h, *ws3l, *ws2h, *ws2l;
    SYMA(xh, g_xh);   SYMA(xl, g_xl);
    SYMA(w1h, g_w1h); SYMA(w1l, g_w1l);
    SYMA(w3h, g_w3h); SYMA(w3l, g_w3l);
    SYMA(w2h, g_w2h); SYMA(w2l, g_w2l);
    SYMA(ws1h, g_ws1h); SYMA(ws1l, g_ws1l);
    SYMA(ws3h, g_ws3h); SYMA(ws3l, g_ws3l);
    SYMA(ws2h, g_ws2h); SYMA(ws2l, g_ws2l);

    conv_launch(x,   xh,   xl,   (size_t)T_ * D_);
    conv_launch(w1,  w1h,  w1l,  (size_t)E_ * H_ * D_);
    conv_launch(w3,  w3h,  w3l,  (size_t)E_ * H_ * D_);
    conv_launch(w2,  w2h,  w2l,  (size_t)E_ * D_ * H_);
    conv_launch(ws1, ws1h, ws1l, (size_t)HS_ * D_);
    conv_launch(ws3, ws3h, ws3l, (size_t)HS_ * D_);
    conv_launch(ws2, ws2h, ws2l, (size_t)D_ * HS_);

    zero_cnt_kernel<<<1, 32>>>();
    gate_kernel<<<T_ / 8, 256>>>(x, gw, gb);

    // phase 1: gate+up+swiglu, routed (z<16) and shared (z=16) merged
    gemm_gu<<<dim3(HS_ / 64, T_ / 64, E_ + 1), 256, GA_SMEM>>>();
    // phase 2: down proj, merged
    gemm_dn<<<dim3(D_ / 128, T_ / 64, E_ + 1), 256, GB_SMEM>>>(out);

    combine_kernel<<<T_, 256>>>(out);
}